// round 16
// baseline (speedup 1.0000x reference)
#include <cuda_runtime.h>
#include <cstdint>
#include <math.h>

#define D_ 512
#define M_ 1200
#define B_ 4
#define L_ 2048
#define NROWS 8192
#define EPSV 1e-5f

#define OUT3_ELEMS (NROWS * D_)          /* 4194304  */
#define SM_ELEMS   (B_ * 6 * L_ * L_)    /* 100663296 */

// ---- static device scratch (no runtime allocations allowed) ----
__device__ float g_v[B_ * M_];
__device__ float g_o[B_ * D_];
__device__ float g_beff[D_];
__device__ float g_beffpart[16 * D_];
__device__ float g_Wpart[4 * D_ * D_];
__device__ float g_Weff[D_ * D_];        // [k][n], tf32(rna)-rounded

// ================= helpers =================
__device__ __forceinline__ uint32_t smem_u32(const void* p) {
    uint32_t a;
    asm("{ .reg .u64 t; cvta.to.shared.u64 t, %1; cvt.u32.u64 %0, t; }"
        : "=r"(a) : "l"(p));
    return a;
}
__device__ __forceinline__ float tf32r(float x) {
    uint32_t u;
    asm("cvt.rna.tf32.f32 %0, %1;" : "=r"(u) : "f"(x));
    return __uint_as_float(u);
}
__device__ __forceinline__ void cp16(uint32_t dst, const void* src) {
    asm volatile("cp.async.cg.shared.global [%0], [%1], 16;"
                 :: "r"(dst), "l"(src));
}
#define CP_COMMIT() asm volatile("cp.async.commit_group;" ::: "memory")
#define CP_WAIT(n)  asm volatile("cp.async.wait_group %0;" :: "n"(n) : "memory")

__device__ __forceinline__ void mma8(float* c, const float* a, const float* b) {
    asm volatile(
        "mma.sync.aligned.m16n8k8.row.col.f32.tf32.tf32.f32 "
        "{%0,%1,%2,%3}, {%4,%5,%6,%7}, {%8,%9}, {%0,%1,%2,%3};"
        : "+f"(c[0]), "+f"(c[1]), "+f"(c[2]), "+f"(c[3])
        : "r"(__float_as_uint(a[0])), "r"(__float_as_uint(a[1])),
          "r"(__float_as_uint(a[2])), "r"(__float_as_uint(a[3])),
          "r"(__float_as_uint(b[0])), "r"(__float_as_uint(b[1])));
}

// ============================================================
// sm = uniform 1/2048 exactly (softmax of row-constant logits).
// PLAIN .wb stores (single change vs R15 record): the same 384MiB
// is rewritten every replay, so dirty-resident L2 lines become
// store-hits on the next replay and never pay DRAM transactions
// during the timed loop (.cs evict-first destroyed this reuse).
// ============================================================
__global__ void fill_sm(float* __restrict__ out) {
    const float v = 1.0f / 2048.0f;
    float4 f = make_float4(v, v, v, v);
    float4* p = (float4*)(out + OUT3_ELEMS);
    int n4 = SM_ELEMS / 4;
    for (int i = blockIdx.x * blockDim.x + threadIdx.x; i < n4;
         i += gridDim.x * blockDim.x)
        p[i] = f;
}

// ============================================================
// v_b[j] = keyval[b] . Wkv[:, M+j] + bkv[M+j]
// ============================================================
__global__ void compute_v(const float* __restrict__ keyval,
                          const float* __restrict__ Wkv,
                          const float* __restrict__ bkv) {
    __shared__ float kv_s[D_];
    int b = blockIdx.y;
    for (int i = threadIdx.x; i < D_; i += blockDim.x)
        kv_s[i] = keyval[b * D_ + i];
    __syncthreads();
    int j = blockIdx.x * blockDim.x + threadIdx.x;
    if (j >= M_) return;
    const float* w = Wkv + M_ + j;
    float acc = bkv[M_ + j];
#pragma unroll 8
    for (int d = 0; d < D_; d++) acc += kv_s[d] * w[d * (2 * M_)];
    g_v[b * M_ + j] = acc;
}

// ============================================================
// o_b[c] = v_b . Wff[:, c] + bff[c]
// ============================================================
__global__ void compute_o(const float* __restrict__ Wff,
                          const float* __restrict__ bff) {
    __shared__ float v_s[M_];
    int b = blockIdx.y;
    for (int i = threadIdx.x; i < M_; i += blockDim.x)
        v_s[i] = g_v[b * M_ + i];
    __syncthreads();
    int c = blockIdx.x * blockDim.x + threadIdx.x;
    float acc = bff[c];
#pragma unroll 8
    for (int j = 0; j < M_; j++) acc += v_s[j] * Wff[j * D_ + c];
    g_o[b * D_ + c] = acc;
}

// ============================================================
// b_eff partials (split-K 16); stays exact fp32
// ============================================================
__global__ void beff_part(const float* __restrict__ b2a,
                          const float* __restrict__ W2b) {
    __shared__ float s[128];
    int kz = blockIdx.x;
    int c = threadIdx.x;
    for (int i = threadIdx.x; i < 128; i += blockDim.x)
        s[i] = b2a[kz * 128 + i];
    __syncthreads();
    float acc = 0.0f;
#pragma unroll 8
    for (int k = 0; k < 128; k++)
        acc += s[k] * W2b[(kz * 128 + k) * D_ + c];
    g_beffpart[kz * D_ + c] = acc;
}

// ============================================================
// weff_mma: W_eff partials via mma.sync tf32, split-K 4
// (R5-measured 16us; low-traffic variant — R15-proven win).
// ============================================================
#define WA_STR 36
#define WB_STR 72
__global__ void __launch_bounds__(256) weff_mma(const float* __restrict__ W2a,
                                                const float* __restrict__ W2b) {
    __shared__ float As[2][64][WA_STR];
    __shared__ float Bs[2][32][WB_STR];
    uint32_t abase = smem_u32(&As[0][0][0]);
    uint32_t bbase = smem_u32(&Bs[0][0][0]);

    int t = threadIdx.x;
    int i0 = blockIdx.y * 64, o0 = blockIdx.x * 64, k0 = blockIdx.z * 512;

    auto loadA = [&](int buf, int kc) {
#pragma unroll
        for (int i = 0; i < 2; i++) {
            int f = t + i * 256;
            int r = f >> 3, c4 = f & 7;
            uint32_t dst = abase + (uint32_t)(buf * 2304 + r * WA_STR + c4 * 4) * 4;
            cp16(dst, W2a + (size_t)(i0 + r) * 2048 + k0 + kc + c4 * 4);
        }
    };
    auto loadB = [&](int buf, int kc) {
#pragma unroll
        for (int i = 0; i < 2; i++) {
            int f = t + i * 256;
            int kr = f >> 4, c4 = f & 15;
            uint32_t dst = bbase + (uint32_t)(buf * 2304 + kr * WB_STR + c4 * 4) * 4;
            cp16(dst, W2b + (size_t)(k0 + kc + kr) * 512 + o0 + c4 * 4);
        }
    };

    loadA(0, 0); loadB(0, 0); CP_COMMIT();

    int wid = t >> 5, lane = t & 31;
    int wm = wid & 1, wn = wid >> 1;
    int lr = lane >> 2, lc = lane & 3;

    float acc[2][2][4] = {};

    for (int ck = 0; ck < 16; ck++) {
        int buf = ck & 1;
        if (ck < 15) {
            loadA(buf ^ 1, (ck + 1) * 32);
            loadB(buf ^ 1, (ck + 1) * 32);
            CP_COMMIT();
            CP_WAIT(1);
        } else {
            CP_WAIT(0);
        }
        __syncthreads();
        const float* Ab = &As[buf][0][0];
        const float* Bb = &Bs[buf][0][0];
#pragma unroll
        for (int kk = 0; kk < 32; kk += 8) {
            float a[2][4];
#pragma unroll
            for (int mf = 0; mf < 2; mf++) {
                int rb = wm * 32 + mf * 16;
                a[mf][0] = tf32r(Ab[(rb + lr) * WA_STR + kk + lc]);
                a[mf][1] = tf32r(Ab[(rb + lr + 8) * WA_STR + kk + lc]);
                a[mf][2] = tf32r(Ab[(rb + lr) * WA_STR + kk + 4 + lc]);
                a[mf][3] = tf32r(Ab[(rb + lr + 8) * WA_STR + kk + 4 + lc]);
            }
            float bf[2][2];
#pragma unroll
            for (int nf = 0; nf < 2; nf++) {
                int n = wn * 16 + nf * 8 + lr;
                bf[nf][0] = tf32r(Bb[(kk + lc) * WB_STR + n]);
                bf[nf][1] = tf32r(Bb[(kk + 4 + lc) * WB_STR + n]);
            }
#pragma unroll
            for (int mf = 0; mf < 2; mf++)
#pragma unroll
                for (int nf = 0; nf < 2; nf++)
                    mma8(acc[mf][nf], a[mf], bf[nf]);
        }
        __syncthreads();
    }

    float* dst = g_Wpart + (size_t)blockIdx.z * (D_ * D_);
#pragma unroll
    for (int mf = 0; mf < 2; mf++) {
#pragma unroll
        for (int j = 0; j < 2; j++) {
            int row = i0 + wm * 32 + mf * 16 + j * 8 + lr;
#pragma unroll
            for (int nf = 0; nf < 2; nf++) {
                int col = o0 + wn * 16 + nf * 8 + lc * 2;
                float2 v = make_float2(acc[mf][nf][j * 2], acc[mf][nf][j * 2 + 1]);
                *(float2*)&dst[(size_t)row * 512 + col] = v;
            }
        }
    }
}

// ============================================================
// reduce: W_eff[k][c] = rna(sum of 4 partials); b_eff = sum + b2b
// ============================================================
__global__ void reduce_k(const float* __restrict__ b2b) {
    if (blockIdx.x < 512) {
        int k = blockIdx.x, c = threadIdx.x;
        float acc = 0.0f;
#pragma unroll
        for (int z = 0; z < 4; z++) acc += g_Wpart[z * (D_ * D_) + k * D_ + c];
        g_Weff[k * D_ + c] = tf32r(acc);
    } else {
        int c = threadIdx.x;
        float acc = b2b[c];
#pragma unroll
        for (int kz = 0; kz < 16; kz++) acc += g_beffpart[kz * D_ + c];
        g_beff[c] = acc;
    }
}

// ============================================================
// gemm_fused: per CTA 64 rows x full 512 cols, 512 threads
//   LN1(query + o_b) -> u in SMEM (exact fp32, resident)
//   y = u @ W_eff  (mma.sync tf32, B double-buffered BK=16)
//   out3 = LN2(u + y + beff) + keyval_b  (fused epilogue)
// ============================================================
#define US 516
#define BSTR 520
#define BS_OFF 33024
#define C_OFF 49664
#define RED_OFF 53248
#define MRS_OFF 54272
#define GF_SMEM (54400 * 4)

__global__ void __launch_bounds__(512, 1) gemm_fused(
    const float* __restrict__ query, const float* __restrict__ keyval,
    const float* __restrict__ g1, const float* __restrict__ b1,
    const float* __restrict__ g2, const float* __restrict__ b2,
    float* __restrict__ out) {
    extern __shared__ float smf[];
    float* u_s  = smf;
    float* Bs   = smf + BS_OFF;
    float* o_s  = smf + C_OFF;
    float* g1_s = o_s + 512;
    float* b1_s = o_s + 1024;
    float* be_s = o_s + 1536;
    float* g2_s = o_s + 2048;
    float* b2_s = o_s + 2560;
    float* kv_s = o_s + 3072;
    float* red  = smf + RED_OFF;
    float* mrs  = smf + MRS_OFF;
    uint32_t sbase = smem_u32(smf);

    int t = threadIdx.x;
    int rowBase = blockIdx.x * 64;
    int b = rowBase >> 11;

    {
        int i = t;
        o_s[i]  = g_o[b * 512 + i];
        g1_s[i] = g1[i]; b1_s[i] = b1[i];
        be_s[i] = g_beff[i];
        g2_s[i] = g2[i]; b2_s[i] = b2[i];
        kv_s[i] = keyval[b * 512 + i];
    }

    auto loadB = [&](int buf, int k0) {
#pragma unroll
        for (int i = 0; i < 4; i++) {
            int f = t + i * 512;
            int kr = f >> 7, c4 = f & 127;
            uint32_t dst = sbase +
                (uint32_t)(BS_OFF + buf * (16 * BSTR) + kr * BSTR + c4 * 4) * 4;
            cp16(dst, g_Weff + (size_t)(k0 + kr) * 512 + c4 * 4);
        }
    };
    loadB(0, 0);  CP_COMMIT();
    loadB(1, 16); CP_COMMIT();
    __syncthreads();

    // ---- LN1: 8 threads per row ----
    {
        int row = t >> 3, sub = t & 7;
        const float* qr = query + (size_t)(rowBase + row) * 512;
        float s1 = 0.f, s2 = 0.f;
#pragma unroll
        for (int j = 0; j < 16; j++) {
            int c = j * 32 + sub * 4;
            float4 v = *(const float4*)(qr + c);
            v.x += o_s[c + 0]; v.y += o_s[c + 1];
            v.z += o_s[c + 2]; v.w += o_s[c + 3];
            *(float4*)(u_s + row * US + c) = v;
            s1 += v.x + v.y + v.z + v.w;
            s2 += v.x * v.x + v.y * v.y + v.z * v.z + v.w * v.w;
        }
#pragma unroll
        for (int off = 1; off < 8; off <<= 1) {
            s1 += __shfl_xor_sync(0xffffffffu, s1, off);
            s2 += __shfl_xor_sync(0xffffffffu, s2, off);
        }
        float m = s1 * (1.0f / 512.0f);
        float rs = rsqrtf(s2 * (1.0f / 512.0f) - m * m + EPSV);
#pragma unroll
        for (int j = 0; j < 16; j++) {
            int c = j * 32 + sub * 4;
            float4 v = *(const float4*)(u_s + row * US + c);
            v.x = (v.x - m) * rs * g1_s[c + 0] + b1_s[c + 0];
            v.y = (v.y - m) * rs * g1_s[c + 1] + b1_s[c + 1];
            v.z = (v.z - m) * rs * g1_s[c + 2] + b1_s[c + 2];
            v.w = (v.w - m) * rs * g1_s[c + 3] + b1_s[c + 3];
            *(float4*)(u_s + row * US + c) = v;
        }
    }

    int wid = t >> 5, lane = t & 31;
    int wm = wid & 1, wn = wid >> 1;
    int lr = lane >> 2, lc = lane & 3;

    float acc[2][8][4] = {};

    for (int ck = 0; ck < 32; ck++) {
        int buf = ck & 1;
        CP_WAIT(1);
        __syncthreads();
        const float* Bb = Bs + buf * (16 * BSTR);
#pragma unroll
        for (int kk = 0; kk < 16; kk += 8) {
            int kg = ck * 16 + kk;
            float a[2][4];
#pragma unroll
            for (int mf = 0; mf < 2; mf++) {
                int rb = wm * 32 + mf * 16;
                a[mf][0] = u_s[(rb + lr) * US + kg + lc];
                a[mf][1] = u_s[(rb + lr + 8) * US + kg + lc];
                a[mf][2] = u_s[(rb + lr) * US + kg + 4 + lc];
                a[mf][3] = u_s[(rb + lr + 8) * US + kg + 4 + lc];
            }
            float bf[8][2];
#pragma unroll
            for (int nf = 0; nf < 8; nf++) {
                int n = wn * 64 + nf * 8 + lr;
                bf[nf][0] = Bb[(kk + lc) * BSTR + n];
                bf[nf][1] = Bb[(kk + 4 + lc) * BSTR + n];
            }
#pragma unroll
            for (int mf = 0; mf < 2; mf++)
#pragma unroll
                for (int nf = 0; nf < 8; nf++)
                    mma8(acc[mf][nf], a[mf], bf[nf]);
        }
        __syncthreads();
        if (ck + 2 < 32) { loadB(buf, (ck + 2) * 16); CP_COMMIT(); }
    }

    // ---- Epilogue: z = u + y + beff; fused LN2; write out ----
#pragma unroll
    for (int mf = 0; mf < 2; mf++) {
#pragma unroll
        for (int j = 0; j < 2; j++) {
            int rowl = wm * 32 + mf * 16 + j * 8 + lr;
            float s1 = 0.f, s2 = 0.f;
#pragma unroll
            for (int nf = 0; nf < 8; nf++) {
                int cl = wn * 64 + nf * 8 + lc * 2;
                float z0 = acc[mf][nf][j * 2 + 0] + u_s[rowl * US + cl]     + be_s[cl];
                float z1 = acc[mf][nf][j * 2 + 1] + u_s[rowl * US + cl + 1] + be_s[cl + 1];
                acc[mf][nf][j * 2 + 0] = z0;
                acc[mf][nf][j * 2 + 1] = z1;
                s1 += z0 + z1;
                s2 += z0 * z0 + z1 * z1;
            }
            s1 += __shfl_xor_sync(0xffffffffu, s1, 1);
            s1 += __shfl_xor_sync(0xffffffffu, s1, 2);
            s2 += __shfl_xor_sync(0xffffffffu, s2, 1);
            s2 += __shfl_xor_sync(0xffffffffu, s2, 2);
            if (lc == 0) {
                red[rowl * 8 + wn] = s1;
                red[512 + rowl * 8 + wn] = s2;
            }
        }
    }
    __syncthreads();
    if (t < 64) {
        float S1 = 0.f, S2 = 0.f;
#pragma unroll
        for (int i = 0; i < 8; i++) {
            S1 += red[t * 8 + i];
            S2 += red[512 + t * 8 + i];
        }
        float m = S1 * (1.0f / 512.0f);
        mrs[t * 2 + 0] = m;
        mrs[t * 2 + 1] = rsqrtf(S2 * (1.0f / 512.0f) - m * m + EPSV);
    }
    __syncthreads();
#pragma unroll
    for (int mf = 0; mf < 2; mf++) {
#pragma unroll
        for (int j = 0; j < 2; j++) {
            int rowl = wm * 32 + mf * 16 + j * 8 + lr;
            float m = mrs[rowl * 2], rs = mrs[rowl * 2 + 1];
            size_t obase = (size_t)(rowBase + rowl) * 512;
#pragma unroll
            for (int nf = 0; nf < 8; nf++) {
                int cl = wn * 64 + nf * 8 + lc * 2;
                float2 o2;
                o2.x = (acc[mf][nf][j * 2 + 0] - m) * rs * g2_s[cl]     + b2_s[cl]     + kv_s[cl];
                o2.y = (acc[mf][nf][j * 2 + 1] - m) * rs * g2_s[cl + 1] + b2_s[cl + 1] + kv_s[cl + 1];
                *(float2*)(out + obase + cl) = o2;
            }
        }
    }
}

// ============================================================
// launch: R15 record topology, single change = fill .cs -> .wb.
// fork(fill sF | weff-chain sW) + v,o on legacy 0 -> join evW ->
// gemm_fused on 0 -> join evFill.
// ============================================================
extern "C" void kernel_launch(void* const* d_in, const int* in_sizes, int n_in,
                              void* d_out, int out_size) {
    const float* query  = (const float*)d_in[0];
    const float* keyval = (const float*)d_in[1];
    const float* Wkv = (const float*)d_in[4];
    const float* bkv = (const float*)d_in[5];
    const float* Wff = (const float*)d_in[6];
    const float* bff = (const float*)d_in[7];
    const float* g1  = (const float*)d_in[8];
    const float* b1  = (const float*)d_in[9];
    const float* W2a = (const float*)d_in[10];
    const float* b2a = (const float*)d_in[11];
    const float* W2b = (const float*)d_in[12];
    const float* b2b = (const float*)d_in[13];
    const float* g2  = (const float*)d_in[14];
    const float* b2  = (const float*)d_in[15];
    float* out = (float*)d_out;

    static cudaStream_t sF = 0, sW = 0;
    static cudaEvent_t evRoot = 0, evFill = 0, evW = 0;
    static int tried = 0;
    if (!tried) {
        tried = 1;
        if (cudaStreamCreateWithFlags(&sF, cudaStreamNonBlocking) != cudaSuccess) sF = 0;
        if (cudaStreamCreateWithFlags(&sW, cudaStreamNonBlocking) != cudaSuccess) sW = 0;
        cudaEventCreateWithFlags(&evRoot, cudaEventDisableTiming);
        cudaEventCreateWithFlags(&evFill, cudaEventDisableTiming);
        cudaEventCreateWithFlags(&evW, cudaEventDisableTiming);
        cudaFuncSetAttribute(gemm_fused, cudaFuncAttributeMaxDynamicSharedMemorySize,
                             GF_SMEM);
    }

    bool fork = (sF != 0) && (sW != 0);
    if (fork) {
        cudaEventRecord(evRoot, 0);
        cudaStreamWaitEvent(sF, evRoot, 0);
        cudaStreamWaitEvent(sW, evRoot, 0);

        fill_sm<<<2048, 256, 0, sF>>>(out);
        cudaEventRecord(evFill, sF);

        beff_part<<<16, 512, 0, sW>>>(b2a, W2b);
        weff_mma<<<dim3(8, 8, 4), 256, 0, sW>>>(W2a, W2b);
        reduce_k<<<513, 512, 0, sW>>>(b2b);
        cudaEventRecord(evW, sW);

        compute_v<<<dim3(5, 4), 256>>>(keyval, Wkv, bkv);
        compute_o<<<dim3(2, 4), 256>>>(Wff, bff);

        cudaStreamWaitEvent(0, evW, 0);
        gemm_fused<<<128, 512, GF_SMEM>>>(query, keyval, g1, b1, g2, b2, out);
        cudaStreamWaitEvent(0, evFill, 0);
    } else {
        fill_sm<<<2048, 256>>>(out);
        beff_part<<<16, 512>>>(b2a, W2b);
        weff_mma<<<dim3(8, 8, 4), 256>>>(W2a, W2b);
        reduce_k<<<513, 512>>>(b2b);
        compute_v<<<dim3(5, 4), 256>>>(keyval, Wkv, bkv);
        compute_o<<<dim3(2, 4), 256>>>(Wff, bff);
        gemm_fused<<<128, 512, GF_SMEM>>>(query, keyval, g1, b1, g2, b2, out);
    }
}

// round 17
// speedup vs baseline: 1.1523x; 1.1523x over previous
#include <cuda_runtime.h>
#include <cstdint>
#include <math.h>

#define D_ 512
#define M_ 1200
#define B_ 4
#define L_ 2048
#define NROWS 8192
#define EPSV 1e-5f

#define OUT3_ELEMS (NROWS * D_)          /* 4194304  */
#define SM_ELEMS   (B_ * 6 * L_ * L_)    /* 100663296 */

// ---- static device scratch (no runtime allocations allowed) ----
__device__ float g_v[B_ * M_];
__device__ float g_o[B_ * D_];
__device__ float g_beff[D_];
__device__ float g_beffpart[16 * D_];
__device__ float g_Wpart[4 * D_ * D_];
__device__ float g_Weff[D_ * D_];        // [k][n], tf32(rna)-rounded

// ================= helpers =================
__device__ __forceinline__ uint32_t smem_u32(const void* p) {
    uint32_t a;
    asm("{ .reg .u64 t; cvta.to.shared.u64 t, %1; cvt.u32.u64 %0, t; }"
        : "=r"(a) : "l"(p));
    return a;
}
__device__ __forceinline__ float tf32r(float x) {
    uint32_t u;
    asm("cvt.rna.tf32.f32 %0, %1;" : "=r"(u) : "f"(x));
    return __uint_as_float(u);
}
__device__ __forceinline__ void cp16(uint32_t dst, const void* src) {
    asm volatile("cp.async.cg.shared.global [%0], [%1], 16;"
                 :: "r"(dst), "l"(src));
}
#define CP_COMMIT() asm volatile("cp.async.commit_group;" ::: "memory")
#define CP_WAIT(n)  asm volatile("cp.async.wait_group %0;" :: "n"(n) : "memory")

__device__ __forceinline__ void mma8(float* c, const float* a, const float* b) {
    asm volatile(
        "mma.sync.aligned.m16n8k8.row.col.f32.tf32.tf32.f32 "
        "{%0,%1,%2,%3}, {%4,%5,%6,%7}, {%8,%9}, {%0,%1,%2,%3};"
        : "+f"(c[0]), "+f"(c[1]), "+f"(c[2]), "+f"(c[3])
        : "r"(__float_as_uint(a[0])), "r"(__float_as_uint(a[1])),
          "r"(__float_as_uint(a[2])), "r"(__float_as_uint(a[3])),
          "r"(__float_as_uint(b[0])), "r"(__float_as_uint(b[1])));
}

// ============================================================
// sm = uniform 1/2048 exactly (softmax of row-constant logits).
// .cs streaming stores — measured fastest steady-state policy
// (.cs ~195us < .wb ~223 < .wt ~260 across R15/R16/R10).
// ============================================================
__global__ void fill_sm(float* __restrict__ out) {
    const float v = 1.0f / 2048.0f;
    float4 f = make_float4(v, v, v, v);
    float4* p = (float4*)(out + OUT3_ELEMS);
    int n4 = SM_ELEMS / 4;
    for (int i = blockIdx.x * blockDim.x + threadIdx.x; i < n4;
         i += gridDim.x * blockDim.x)
        __stcs(&p[i], f);
}

// ============================================================
// v_b[j] = keyval[b] . Wkv[:, M+j] + bkv[M+j]
// ============================================================
__global__ void compute_v(const float* __restrict__ keyval,
                          const float* __restrict__ Wkv,
                          const float* __restrict__ bkv) {
    __shared__ float kv_s[D_];
    int b = blockIdx.y;
    for (int i = threadIdx.x; i < D_; i += blockDim.x)
        kv_s[i] = keyval[b * D_ + i];
    __syncthreads();
    int j = blockIdx.x * blockDim.x + threadIdx.x;
    if (j >= M_) return;
    const float* w = Wkv + M_ + j;
    float acc = bkv[M_ + j];
#pragma unroll 8
    for (int d = 0; d < D_; d++) acc += kv_s[d] * w[d * (2 * M_)];
    g_v[b * M_ + j] = acc;
}

// ============================================================
// o_b[c] = v_b . Wff[:, c] + bff[c]
// ============================================================
__global__ void compute_o(const float* __restrict__ Wff,
                          const float* __restrict__ bff) {
    __shared__ float v_s[M_];
    int b = blockIdx.y;
    for (int i = threadIdx.x; i < M_; i += blockDim.x)
        v_s[i] = g_v[b * M_ + i];
    __syncthreads();
    int c = blockIdx.x * blockDim.x + threadIdx.x;
    float acc = bff[c];
#pragma unroll 8
    for (int j = 0; j < M_; j++) acc += v_s[j] * Wff[j * D_ + c];
    g_o[b * D_ + c] = acc;
}

// ============================================================
// b_eff partials (split-K 16); stays exact fp32
// ============================================================
__global__ void beff_part(const float* __restrict__ b2a,
                          const float* __restrict__ W2b) {
    __shared__ float s[128];
    int kz = blockIdx.x;
    int c = threadIdx.x;
    for (int i = threadIdx.x; i < 128; i += blockDim.x)
        s[i] = b2a[kz * 128 + i];
    __syncthreads();
    float acc = 0.0f;
#pragma unroll 8
    for (int k = 0; k < 128; k++)
        acc += s[k] * W2b[(kz * 128 + k) * D_ + c];
    g_beffpart[kz * D_ + c] = acc;
}

// ============================================================
// weff_mma: W_eff partials via mma.sync tf32, split-K 4
// (low-traffic variant — R15-proven win vs fp32 weff_part).
// ============================================================
#define WA_STR 36
#define WB_STR 72
__global__ void __launch_bounds__(256) weff_mma(const float* __restrict__ W2a,
                                                const float* __restrict__ W2b) {
    __shared__ float As[2][64][WA_STR];
    __shared__ float Bs[2][32][WB_STR];
    uint32_t abase = smem_u32(&As[0][0][0]);
    uint32_t bbase = smem_u32(&Bs[0][0][0]);

    int t = threadIdx.x;
    int i0 = blockIdx.y * 64, o0 = blockIdx.x * 64, k0 = blockIdx.z * 512;

    auto loadA = [&](int buf, int kc) {
#pragma unroll
        for (int i = 0; i < 2; i++) {
            int f = t + i * 256;
            int r = f >> 3, c4 = f & 7;
            uint32_t dst = abase + (uint32_t)(buf * 2304 + r * WA_STR + c4 * 4) * 4;
            cp16(dst, W2a + (size_t)(i0 + r) * 2048 + k0 + kc + c4 * 4);
        }
    };
    auto loadB = [&](int buf, int kc) {
#pragma unroll
        for (int i = 0; i < 2; i++) {
            int f = t + i * 256;
            int kr = f >> 4, c4 = f & 15;
            uint32_t dst = bbase + (uint32_t)(buf * 2304 + kr * WB_STR + c4 * 4) * 4;
            cp16(dst, W2b + (size_t)(k0 + kc + kr) * 512 + o0 + c4 * 4);
        }
    };

    loadA(0, 0); loadB(0, 0); CP_COMMIT();

    int wid = t >> 5, lane = t & 31;
    int wm = wid & 1, wn = wid >> 1;
    int lr = lane >> 2, lc = lane & 3;

    float acc[2][2][4] = {};

    for (int ck = 0; ck < 16; ck++) {
        int buf = ck & 1;
        if (ck < 15) {
            loadA(buf ^ 1, (ck + 1) * 32);
            loadB(buf ^ 1, (ck + 1) * 32);
            CP_COMMIT();
            CP_WAIT(1);
        } else {
            CP_WAIT(0);
        }
        __syncthreads();
        const float* Ab = &As[buf][0][0];
        const float* Bb = &Bs[buf][0][0];
#pragma unroll
        for (int kk = 0; kk < 32; kk += 8) {
            float a[2][4];
#pragma unroll
            for (int mf = 0; mf < 2; mf++) {
                int rb = wm * 32 + mf * 16;
                a[mf][0] = tf32r(Ab[(rb + lr) * WA_STR + kk + lc]);
                a[mf][1] = tf32r(Ab[(rb + lr + 8) * WA_STR + kk + lc]);
                a[mf][2] = tf32r(Ab[(rb + lr) * WA_STR + kk + 4 + lc]);
                a[mf][3] = tf32r(Ab[(rb + lr + 8) * WA_STR + kk + 4 + lc]);
            }
            float bf[2][2];
#pragma unroll
            for (int nf = 0; nf < 2; nf++) {
                int n = wn * 16 + nf * 8 + lr;
                bf[nf][0] = tf32r(Bb[(kk + lc) * WB_STR + n]);
                bf[nf][1] = tf32r(Bb[(kk + 4 + lc) * WB_STR + n]);
            }
#pragma unroll
            for (int mf = 0; mf < 2; mf++)
#pragma unroll
                for (int nf = 0; nf < 2; nf++)
                    mma8(acc[mf][nf], a[mf], bf[nf]);
        }
        __syncthreads();
    }

    float* dst = g_Wpart + (size_t)blockIdx.z * (D_ * D_);
#pragma unroll
    for (int mf = 0; mf < 2; mf++) {
#pragma unroll
        for (int j = 0; j < 2; j++) {
            int row = i0 + wm * 32 + mf * 16 + j * 8 + lr;
#pragma unroll
            for (int nf = 0; nf < 2; nf++) {
                int col = o0 + wn * 16 + nf * 8 + lc * 2;
                float2 v = make_float2(acc[mf][nf][j * 2], acc[mf][nf][j * 2 + 1]);
                *(float2*)&dst[(size_t)row * 512 + col] = v;
            }
        }
    }
}

// ============================================================
// reduce: W_eff[k][c] = rna(sum of 4 partials); b_eff = sum + b2b
// ============================================================
__global__ void reduce_k(const float* __restrict__ b2b) {
    if (blockIdx.x < 512) {
        int k = blockIdx.x, c = threadIdx.x;
        float acc = 0.0f;
#pragma unroll
        for (int z = 0; z < 4; z++) acc += g_Wpart[z * (D_ * D_) + k * D_ + c];
        g_Weff[k * D_ + c] = tf32r(acc);
    } else {
        int c = threadIdx.x;
        float acc = b2b[c];
#pragma unroll
        for (int kz = 0; kz < 16; kz++) acc += g_beffpart[kz * D_ + c];
        g_beff[c] = acc;
    }
}

// ============================================================
// gemm_fused: per CTA 64 rows x full 512 cols, 512 threads
//   LN1(query + o_b) -> u in SMEM (exact fp32, resident)
//   y = u @ W_eff  (mma.sync tf32, B double-buffered BK=16)
//   out3 = LN2(u + y + beff) + keyval_b  (fused epilogue)
// ============================================================
#define US 516
#define BSTR 520
#define BS_OFF 33024
#define C_OFF 49664
#define RED_OFF 53248
#define MRS_OFF 54272
#define GF_SMEM (54400 * 4)

__global__ void __launch_bounds__(512, 1) gemm_fused(
    const float* __restrict__ query, const float* __restrict__ keyval,
    const float* __restrict__ g1, const float* __restrict__ b1,
    const float* __restrict__ g2, const float* __restrict__ b2,
    float* __restrict__ out) {
    extern __shared__ float smf[];
    float* u_s  = smf;
    float* Bs   = smf + BS_OFF;
    float* o_s  = smf + C_OFF;
    float* g1_s = o_s + 512;
    float* b1_s = o_s + 1024;
    float* be_s = o_s + 1536;
    float* g2_s = o_s + 2048;
    float* b2_s = o_s + 2560;
    float* kv_s = o_s + 3072;
    float* red  = smf + RED_OFF;
    float* mrs  = smf + MRS_OFF;
    uint32_t sbase = smem_u32(smf);

    int t = threadIdx.x;
    int rowBase = blockIdx.x * 64;
    int b = rowBase >> 11;

    {
        int i = t;
        o_s[i]  = g_o[b * 512 + i];
        g1_s[i] = g1[i]; b1_s[i] = b1[i];
        be_s[i] = g_beff[i];
        g2_s[i] = g2[i]; b2_s[i] = b2[i];
        kv_s[i] = keyval[b * 512 + i];
    }

    auto loadB = [&](int buf, int k0) {
#pragma unroll
        for (int i = 0; i < 4; i++) {
            int f = t + i * 512;
            int kr = f >> 7, c4 = f & 127;
            uint32_t dst = sbase +
                (uint32_t)(BS_OFF + buf * (16 * BSTR) + kr * BSTR + c4 * 4) * 4;
            cp16(dst, g_Weff + (size_t)(k0 + kr) * 512 + c4 * 4);
        }
    };
    loadB(0, 0);  CP_COMMIT();
    loadB(1, 16); CP_COMMIT();
    __syncthreads();

    // ---- LN1: 8 threads per row ----
    {
        int row = t >> 3, sub = t & 7;
        const float* qr = query + (size_t)(rowBase + row) * 512;
        float s1 = 0.f, s2 = 0.f;
#pragma unroll
        for (int j = 0; j < 16; j++) {
            int c = j * 32 + sub * 4;
            float4 v = *(const float4*)(qr + c);
            v.x += o_s[c + 0]; v.y += o_s[c + 1];
            v.z += o_s[c + 2]; v.w += o_s[c + 3];
            *(float4*)(u_s + row * US + c) = v;
            s1 += v.x + v.y + v.z + v.w;
            s2 += v.x * v.x + v.y * v.y + v.z * v.z + v.w * v.w;
        }
#pragma unroll
        for (int off = 1; off < 8; off <<= 1) {
            s1 += __shfl_xor_sync(0xffffffffu, s1, off);
            s2 += __shfl_xor_sync(0xffffffffu, s2, off);
        }
        float m = s1 * (1.0f / 512.0f);
        float rs = rsqrtf(s2 * (1.0f / 512.0f) - m * m + EPSV);
#pragma unroll
        for (int j = 0; j < 16; j++) {
            int c = j * 32 + sub * 4;
            float4 v = *(const float4*)(u_s + row * US + c);
            v.x = (v.x - m) * rs * g1_s[c + 0] + b1_s[c + 0];
            v.y = (v.y - m) * rs * g1_s[c + 1] + b1_s[c + 1];
            v.z = (v.z - m) * rs * g1_s[c + 2] + b1_s[c + 2];
            v.w = (v.w - m) * rs * g1_s[c + 3] + b1_s[c + 3];
            *(float4*)(u_s + row * US + c) = v;
        }
    }

    int wid = t >> 5, lane = t & 31;
    int wm = wid & 1, wn = wid >> 1;
    int lr = lane >> 2, lc = lane & 3;

    float acc[2][8][4] = {};

    for (int ck = 0; ck < 32; ck++) {
        int buf = ck & 1;
        CP_WAIT(1);
        __syncthreads();
        const float* Bb = Bs + buf * (16 * BSTR);
#pragma unroll
        for (int kk = 0; kk < 16; kk += 8) {
            int kg = ck * 16 + kk;
            float a[2][4];
#pragma unroll
            for (int mf = 0; mf < 2; mf++) {
                int rb = wm * 32 + mf * 16;
                a[mf][0] = u_s[(rb + lr) * US + kg + lc];
                a[mf][1] = u_s[(rb + lr + 8) * US + kg + lc];
                a[mf][2] = u_s[(rb + lr) * US + kg + 4 + lc];
                a[mf][3] = u_s[(rb + lr + 8) * US + kg + 4 + lc];
            }
            float bf[8][2];
#pragma unroll
            for (int nf = 0; nf < 8; nf++) {
                int n = wn * 64 + nf * 8 + lr;
                bf[nf][0] = Bb[(kk + lc) * BSTR + n];
                bf[nf][1] = Bb[(kk + 4 + lc) * BSTR + n];
            }
#pragma unroll
            for (int mf = 0; mf < 2; mf++)
#pragma unroll
                for (int nf = 0; nf < 8; nf++)
                    mma8(acc[mf][nf], a[mf], bf[nf]);
        }
        __syncthreads();
        if (ck + 2 < 32) { loadB(buf, (ck + 2) * 16); CP_COMMIT(); }
    }

    // ---- Epilogue: z = u + y + beff; fused LN2; write out ----
#pragma unroll
    for (int mf = 0; mf < 2; mf++) {
#pragma unroll
        for (int j = 0; j < 2; j++) {
            int rowl = wm * 32 + mf * 16 + j * 8 + lr;
            float s1 = 0.f, s2 = 0.f;
#pragma unroll
            for (int nf = 0; nf < 8; nf++) {
                int cl = wn * 64 + nf * 8 + lc * 2;
                float z0 = acc[mf][nf][j * 2 + 0] + u_s[rowl * US + cl]     + be_s[cl];
                float z1 = acc[mf][nf][j * 2 + 1] + u_s[rowl * US + cl + 1] + be_s[cl + 1];
                acc[mf][nf][j * 2 + 0] = z0;
                acc[mf][nf][j * 2 + 1] = z1;
                s1 += z0 + z1;
                s2 += z0 * z0 + z1 * z1;
            }
            s1 += __shfl_xor_sync(0xffffffffu, s1, 1);
            s1 += __shfl_xor_sync(0xffffffffu, s1, 2);
            s2 += __shfl_xor_sync(0xffffffffu, s2, 1);
            s2 += __shfl_xor_sync(0xffffffffu, s2, 2);
            if (lc == 0) {
                red[rowl * 8 + wn] = s1;
                red[512 + rowl * 8 + wn] = s2;
            }
        }
    }
    __syncthreads();
    if (t < 64) {
        float S1 = 0.f, S2 = 0.f;
#pragma unroll
        for (int i = 0; i < 8; i++) {
            S1 += red[t * 8 + i];
            S2 += red[512 + t * 8 + i];
        }
        float m = S1 * (1.0f / 512.0f);
        mrs[t * 2 + 0] = m;
        mrs[t * 2 + 1] = rsqrtf(S2 * (1.0f / 512.0f) - m * m + EPSV);
    }
    __syncthreads();
#pragma unroll
    for (int mf = 0; mf < 2; mf++) {
#pragma unroll
        for (int j = 0; j < 2; j++) {
            int rowl = wm * 32 + mf * 16 + j * 8 + lr;
            float m = mrs[rowl * 2], rs = mrs[rowl * 2 + 1];
            size_t obase = (size_t)(rowBase + rowl) * 512;
#pragma unroll
            for (int nf = 0; nf < 8; nf++) {
                int cl = wn * 64 + nf * 8 + lc * 2;
                float2 o2;
                o2.x = (acc[mf][nf][j * 2 + 0] - m) * rs * g2_s[cl]     + b2_s[cl]     + kv_s[cl];
                o2.y = (acc[mf][nf][j * 2 + 1] - m) * rs * g2_s[cl + 1] + b2_s[cl + 1] + kv_s[cl + 1];
                *(float2*)(out + obase + cl) = o2;
            }
        }
    }
}

// ============================================================
// launch: R15 record configuration (200.8us), byte-exact.
// fork(fill sF | weff-chain sW) + v,o on legacy 0 -> join evW ->
// gemm_fused on 0 -> join evFill.
// ============================================================
extern "C" void kernel_launch(void* const* d_in, const int* in_sizes, int n_in,
                              void* d_out, int out_size) {
    const float* query  = (const float*)d_in[0];
    const float* keyval = (const float*)d_in[1];
    const float* Wkv = (const float*)d_in[4];
    const float* bkv = (const float*)d_in[5];
    const float* Wff = (const float*)d_in[6];
    const float* bff = (const float*)d_in[7];
    const float* g1  = (const float*)d_in[8];
    const float* b1  = (const float*)d_in[9];
    const float* W2a = (const float*)d_in[10];
    const float* b2a = (const float*)d_in[11];
    const float* W2b = (const float*)d_in[12];
    const float* b2b = (const float*)d_in[13];
    const float* g2  = (const float*)d_in[14];
    const float* b2  = (const float*)d_in[15];
    float* out = (float*)d_out;

    static cudaStream_t sF = 0, sW = 0;
    static cudaEvent_t evRoot = 0, evFill = 0, evW = 0;
    static int tried = 0;
    if (!tried) {
        tried = 1;
        if (cudaStreamCreateWithFlags(&sF, cudaStreamNonBlocking) != cudaSuccess) sF = 0;
        if (cudaStreamCreateWithFlags(&sW, cudaStreamNonBlocking) != cudaSuccess) sW = 0;
        cudaEventCreateWithFlags(&evRoot, cudaEventDisableTiming);
        cudaEventCreateWithFlags(&evFill, cudaEventDisableTiming);
        cudaEventCreateWithFlags(&evW, cudaEventDisableTiming);
        cudaFuncSetAttribute(gemm_fused, cudaFuncAttributeMaxDynamicSharedMemorySize,
                             GF_SMEM);
    }

    bool fork = (sF != 0) && (sW != 0);
    if (fork) {
        cudaEventRecord(evRoot, 0);
        cudaStreamWaitEvent(sF, evRoot, 0);
        cudaStreamWaitEvent(sW, evRoot, 0);

        fill_sm<<<2048, 256, 0, sF>>>(out);
        cudaEventRecord(evFill, sF);

        beff_part<<<16, 512, 0, sW>>>(b2a, W2b);
        weff_mma<<<dim3(8, 8, 4), 256, 0, sW>>>(W2a, W2b);
        reduce_k<<<513, 512, 0, sW>>>(b2b);
        cudaEventRecord(evW, sW);

        compute_v<<<dim3(5, 4), 256>>>(keyval, Wkv, bkv);
        compute_o<<<dim3(2, 4), 256>>>(Wff, bff);

        cudaStreamWaitEvent(0, evW, 0);
        gemm_fused<<<128, 512, GF_SMEM>>>(query, keyval, g1, b1, g2, b2, out);
        cudaStreamWaitEvent(0, evFill, 0);
    } else {
        fill_sm<<<2048, 256>>>(out);
        beff_part<<<16, 512>>>(b2a, W2b);
        weff_mma<<<dim3(8, 8, 4), 256>>>(W2a, W2b);
        reduce_k<<<513, 512>>>(b2b);
        compute_v<<<dim3(5, 4), 256>>>(keyval, Wkv, bkv);
        compute_o<<<dim3(2, 4), 256>>>(Wff, bff);
        gemm_fused<<<128, 512, GF_SMEM>>>(query, keyval, g1, b1, g2, b2, out);
    }
}